// round 9
// baseline (speedup 1.0000x reference)
#include <cuda_runtime.h>
#include <cuda_bf16.h>
#include <cstdint>
#include <cstddef>

// ---------------- problem dims ----------------
static constexpr int Mdim = 8192;   // B*T
static constexpr int Ndim = 1024;   // codebook rows
static constexpr int Kdim = 512;    // D

static constexpr int MT = 128;
static constexpr int NT = 128;
static constexpr int THREADS = 256;      // 8 warps: 4 (M) x 2 (N), 32x64 each
static constexpr int NKB = Kdim / 16;    // 32 k16 blocks
static constexpr int NMB = Mdim / 16;    // 512 m16 blocks
static constexpr int NNB = Ndim / 16;    // 64 n16 blocks
static constexpr int SM_EPI = 128 * 132 * 4;   // epilogue staging (67.6 KB)

__device__ float g_xsq[Mdim];
__device__ float g_csq[Ndim];
// fragment-linear layouts: record (blk16 x k16) = 32 lanes x uint4 (512B)
__device__ uint4 g_af[(size_t)NMB * NKB * 32];   // 8 MB
__device__ uint4 g_bf[(size_t)NNB * NKB * 32];   // 1 MB

// ---------------- helpers ----------------
__device__ __forceinline__ uint32_t pack_bf16x2(float a, float b) {
    uint32_t r;
    asm("cvt.rn.bf16x2.f32 %0, %1, %2;" : "=r"(r) : "f"(b), "f"(a));
    return r;
}
__device__ __forceinline__ void mma_bf16(float* c, const uint32_t* a,
                                         uint32_t b0, uint32_t b1) {
    asm volatile(
        "mma.sync.aligned.m16n8k16.row.col.f32.bf16.bf16.f32 "
        "{%0,%1,%2,%3}, {%4,%5,%6,%7}, {%8,%9}, {%0,%1,%2,%3};"
        : "+f"(c[0]), "+f"(c[1]), "+f"(c[2]), "+f"(c[3])
        : "r"(a[0]), "r"(a[1]), "r"(a[2]), "r"(a[3]), "r"(b0), "r"(b1));
}

// ---------------- row norms (fp32, exact) ----------------
__global__ void __launch_bounds__(256) rowsq_kernel(const float* __restrict__ x,
                                                    const float* __restrict__ cb) {
    int row  = blockIdx.x * 8 + (threadIdx.x >> 5);
    int lane = threadIdx.x & 31;
    const float4* src;
    float* dst;
    if (row < Mdim) {
        src = reinterpret_cast<const float4*>(x) + (size_t)row * (Kdim / 4);
        dst = g_xsq + row;
    } else if (row < Mdim + Ndim) {
        int r = row - Mdim;
        src = reinterpret_cast<const float4*>(cb) + (size_t)r * (Kdim / 4);
        dst = g_csq + r;
    } else return;
    float s = 0.f;
    #pragma unroll
    for (int i = lane; i < Kdim / 4; i += 32) {
        float4 v = src[i];
        s += v.x * v.x + v.y * v.y + v.z * v.z + v.w * v.w;
    }
    #pragma unroll
    for (int o = 16; o; o >>= 1) s += __shfl_xor_sync(0xffffffffu, s, o);
    if (lane == 0) *dst = s;
}

// ------- frag prep: pack A / B 16x16 blocks into mma lane layout -------
// A record lane l (matches mma A frag a0..a3):
//   x = M[r][k], y = M[r+8][k], z = M[r][k+8], w = M[r+8][k+8]
//   where r = blk16 + (l>>2), k = kb16 + (l&3)*2  (each reg = bf16x2 over k,k+1)
// B record lane l (PAIRED FOR (b0,b1) CONSUMPTION — differs from A!):
//   x = B[n][k], y = B[n][k+8], z = B[n+8][k], w = B[n+8][k+8]
//   so mma uses (x,y) for n-block 0-7 and (z,w) for n-block 8-15.
__global__ void __launch_bounds__(256) frag_kernel(const float* __restrict__ x,
                                                   const float* __restrict__ cb) {
    int rw   = blockIdx.x * 8 + (threadIdx.x >> 5);  // global warp = record id
    int lane = threadIdx.x & 31;
    const float* src;
    uint4* dst;
    int blk, kb;
    bool isB;
    if (rw < NMB * NKB) {
        blk = rw >> 5; kb = rw & 31;
        src = x;
        dst = g_af + (size_t)rw * 32;
        isB = false;
    } else {
        int rb = rw - NMB * NKB;
        if (rb >= NNB * NKB) return;
        blk = rb >> 5; kb = rb & 31;
        src = cb;
        dst = g_bf + (size_t)rb * 32;
        isB = true;
    }
    const int r0 = blk * 16 + (lane >> 2);
    const int c0 = kb * 16 + (lane & 3) * 2;
    const float2* p00 = reinterpret_cast<const float2*>(src + (size_t)r0 * Kdim + c0);
    const float2* p10 = reinterpret_cast<const float2*>(src + (size_t)(r0 + 8) * Kdim + c0);
    float2 a00 = p00[0];
    float2 a01 = p00[4];          // +8 cols (same row, k+8)
    float2 a10 = p10[0];          // row+8, k
    float2 a11 = p10[4];          // row+8, k+8
    uint4 o;
    if (!isB) {
        o.x = pack_bf16x2(a00.x, a00.y);
        o.y = pack_bf16x2(a10.x, a10.y);
        o.z = pack_bf16x2(a01.x, a01.y);
        o.w = pack_bf16x2(a11.x, a11.y);
    } else {
        o.x = pack_bf16x2(a00.x, a00.y);   // n,   k
        o.y = pack_bf16x2(a01.x, a01.y);   // n,   k+8
        o.z = pack_bf16x2(a10.x, a10.y);   // n+8, k
        o.w = pack_bf16x2(a11.x, a11.y);   // n+8, k+8
    }
    dst[lane] = o;
}

// ---------------- GEMM: no smem / no barriers in mainloop ----------------
__global__ void __launch_bounds__(THREADS, 2)
gemm_kernel(const float* __restrict__ precision, float* __restrict__ out) {
    extern __shared__ char smem[];
    const int tid  = threadIdx.x;
    const int lane = tid & 31;
    const int w    = tid >> 5;
    const int wm   = w >> 1;          // 0..3
    const int wn   = w & 1;           // 0..1
    const int m0 = blockIdx.y * MT;
    const int n0 = blockIdx.x * NT;

    // record indices (uint4 units): record (blk*NKB + ks), lane offset
    const int mb0 = blockIdx.y * 8 + wm * 2;
    const int nb0 = blockIdx.x * 8 + wn * 4;
    uint32_t iA[2], iB[4];
    #pragma unroll
    for (int mf = 0; mf < 2; mf++)  iA[mf] = ((uint32_t)(mb0 + mf) * NKB) * 32 + lane;
    #pragma unroll
    for (int nf2 = 0; nf2 < 4; nf2++) iB[nf2] = ((uint32_t)(nb0 + nf2) * NKB) * 32 + lane;

    float acc[2][8][4];
    #pragma unroll
    for (int mf = 0; mf < 2; mf++)
        #pragma unroll
        for (int nf = 0; nf < 8; nf++)
            #pragma unroll
            for (int q = 0; q < 4; q++) acc[mf][nf][q] = 0.f;

    uint4 Ab[2][2], Bb[2][4];   // [buf][frag]
    #pragma unroll
    for (int mf = 0; mf < 2; mf++)  Ab[0][mf] = g_af[iA[mf]];
    #pragma unroll
    for (int nf2 = 0; nf2 < 4; nf2++) Bb[0][nf2] = g_bf[iB[nf2]];

    #pragma unroll 2
    for (int ks = 0; ks < NKB; ks++) {
        const int cur = ks & 1, nxt = cur ^ 1;
        if (ks < NKB - 1) {
            #pragma unroll
            for (int mf = 0; mf < 2; mf++)
                Ab[nxt][mf] = g_af[iA[mf] + (uint32_t)(ks + 1) * 32];
            #pragma unroll
            for (int nf2 = 0; nf2 < 4; nf2++)
                Bb[nxt][nf2] = g_bf[iB[nf2] + (uint32_t)(ks + 1) * 32];
        }
        #pragma unroll
        for (int mf = 0; mf < 2; mf++) {
            const uint32_t* a = reinterpret_cast<const uint32_t*>(&Ab[cur][mf]);
            #pragma unroll
            for (int nf2 = 0; nf2 < 4; nf2++) {
                mma_bf16(acc[mf][nf2 * 2 + 0], a, Bb[cur][nf2].x, Bb[cur][nf2].y);
                mma_bf16(acc[mf][nf2 * 2 + 1], a, Bb[cur][nf2].z, Bb[cur][nf2].w);
            }
        }
    }

    // ---------------- epilogue (smem only used here) ----------------
    float* sE = reinterpret_cast<float*>(smem);   // [128][132]
    const int erow = wm * 32 + (lane >> 2);
    const int ecol = wn * 64 + (lane & 3) * 2;
    #pragma unroll
    for (int mf = 0; mf < 2; mf++) {
        #pragma unroll
        for (int nf = 0; nf < 8; nf++) {
            float2* p0 = reinterpret_cast<float2*>(
                &sE[(erow + mf * 16) * 132 + ecol + nf * 8]);
            float2* p1 = reinterpret_cast<float2*>(
                &sE[(erow + mf * 16 + 8) * 132 + ecol + nf * 8]);
            *p0 = make_float2(acc[mf][nf][0], acc[mf][nf][1]);
            *p1 = make_float2(acc[mf][nf][2], acc[mf][nf][3]);
        }
    }
    __syncthreads();

    const float prec = precision[0];
    const int cj = (tid & 31) * 4;              // col group of 4
    const float4 cs = *reinterpret_cast<const float4*>(&g_csq[n0 + cj]);
    #pragma unroll 4
    for (int it = 0; it < 16; it++) {
        const int r = (tid >> 5) + it * 8;      // 0..127
        const float xs = g_xsq[m0 + r];
        const float* sp = &sE[r * 132 + cj];
        float4 v;
        v.x = prec * (2.f * sp[0] - xs - cs.x);
        v.y = prec * (2.f * sp[1] - xs - cs.y);
        v.z = prec * (2.f * sp[2] - xs - cs.z);
        v.w = prec * (2.f * sp[3] - xs - cs.w);
        *reinterpret_cast<float4*>(&out[(size_t)(m0 + r) * Ndim + n0 + cj]) = v;
    }
}

// ---------------- launch ----------------
extern "C" void kernel_launch(void* const* d_in, const int* in_sizes, int n_in,
                              void* d_out, int out_size) {
    (void)in_sizes; (void)n_in; (void)out_size;
    const float* x    = (const float*)d_in[0];
    const float* cb   = (const float*)d_in[1];
    const float* prec = (const float*)d_in[2];
    float* out = (float*)d_out;

    cudaFuncSetAttribute(gemm_kernel,
                         cudaFuncAttributeMaxDynamicSharedMemorySize, SM_EPI);

    rowsq_kernel<<<(Mdim + Ndim) / 8, 256>>>(x, cb);
    frag_kernel<<<(NMB * NKB + NNB * NKB) / 8, 256>>>(x, cb);
    dim3 grid(Ndim / NT, Mdim / MT);   // (8, 64) = 512 CTAs
    gemm_kernel<<<grid, THREADS, SM_EPI>>>(prec, out);
}